// round 14
// baseline (speedup 1.0000x reference)
#include <cuda_runtime.h>
#include <cuda_fp16.h>
#include <math.h>

typedef unsigned int u32;

#define DOF    7
#define NB     5
#define KDIM   256
#define OUTC   42
#define RPT    32            // rows per tile
#define BATCH  65536
#define NTILES (BATCH / RPT) // 2048
#define TPB    256

// ---- smem layout (bytes). Unpadded 512B rows, XOR-swizzled:
// phys16(r, c) = (c ^ (r & 7)), 16B units; conflict-free STS/LDSM/cp.async.
#define A0     0             // 32 x 512 = 16384
#define A1     16384         // -> 32768
#define B_HI   32768         // 48 x 512 = 24576 -> 57344 (fp16 W, resident)
#define CS     57344         // 2 x (32*50*4) = 12800 -> 70144
#define EB     70144         // 32*77*4 = 9856 -> 80000
#define SMEM_TOTAL 80000     // x2 CTAs/SM

// Pre-converted, PRE-SWIZZLED W tile (exact smem byte layout, 48x512B)
__device__ __align__(16) unsigned short g_Bhi[48 * 256];
__device__ __align__(16) float g_bias48[48];

// DMP linear map: y[t] = A[t] . [y0, g, u0..u4, 1]
__constant__ float c_A[11 * 8];

__device__ __forceinline__ u32 sm2u32(const void* p) {
    u32 a; asm("{.reg .u64 t; cvta.to.shared.u64 t,%1; cvt.u32.u64 %0,t;}"
               : "=r"(a) : "l"(p));
    return a;
}
__device__ __forceinline__ void ldsm4(u32 addr, u32& r0, u32& r1, u32& r2, u32& r3) {
    asm volatile("ldmatrix.sync.aligned.m8n8.x4.shared.b16 {%0,%1,%2,%3},[%4];"
                 : "=r"(r0), "=r"(r1), "=r"(r2), "=r"(r3) : "r"(addr));
}
__device__ __forceinline__ void ldsm2(u32 addr, u32& r0, u32& r1) {
    asm volatile("ldmatrix.sync.aligned.m8n8.x2.shared.b16 {%0,%1},[%2];"
                 : "=r"(r0), "=r"(r1) : "r"(addr));
}
__device__ __forceinline__ void mma16816(float* c, const u32* a, u32 b0, u32 b1) {
    asm volatile(
        "mma.sync.aligned.m16n8k16.row.col.f32.f16.f16.f32 "
        "{%0,%1,%2,%3},{%4,%5,%6,%7},{%8,%9},{%0,%1,%2,%3};"
        : "+f"(c[0]), "+f"(c[1]), "+f"(c[2]), "+f"(c[3])
        : "r"(a[0]), "r"(a[1]), "r"(a[2]), "r"(a[3]), "r"(b0), "r"(b1));
}
__device__ __forceinline__ void cp_async16(u32 dst, const void* src) {
    asm volatile("cp.async.cg.shared.global [%0],[%1],16;" :: "r"(dst), "l"(src));
}

// convert 8 float4 (one 32-row tile slice per thread) into swizzled A buffer
__device__ __forceinline__ void convert_sts(char* sm, u32 abase, const float4* v,
                                            int tid) {
    #pragma unroll
    for (int j = 0; j < 8; j++) {
        int idx = tid + j * TPB;
        int r = idx >> 6, k4 = idx & 63;
        __half2 h01 = __floats2half2_rn(v[j].x, v[j].y);
        __half2 h23 = __floats2half2_rn(v[j].z, v[j].w);
        u32 off = (u32)(r * 512) + ((((u32)k4 >> 1) ^ ((u32)r & 7u)) << 4)
                + ((u32)k4 & 1u) * 8u;
        *(uint2*)(sm + abase + off) =
            make_uint2(*(const u32*)&h01, *(const u32*)&h23);
    }
}

// ---------------------------------------------------------------------------
// Prep (once): W -> fp16, stored pre-swizzled:
//   short-off(n, k) = n*256 + (((k>>3) ^ (n&7)) << 3) + (k&7)
// ---------------------------------------------------------------------------
__global__ void prep_w_kernel(const float* __restrict__ W,
                              const float* __restrict__ bias)
{
    int gid = blockIdx.x * 256 + threadIdx.x;   // 48*256 = 12288 threads
    int n = gid >> 8, k = gid & 255;
    unsigned short hi = 0;
    if (n < OUTC) {
        float w = __ldg(W + k * OUTC + n);
        __half h = __float2half_rn(w);
        hi = *(const unsigned short*)&h;
    }
    int off = n * 256 + (((k >> 3) ^ (n & 7)) << 3) + (k & 7);
    g_Bhi[off] = hi;
    if (gid < 48) g_bias48[gid] = (gid < OUTC) ? __ldg(bias + gid) : 0.0f;
}

// ---------------------------------------------------------------------------
// Persistent fused kernel: each CTA loads B once and streams ~7 tiles.
// ---------------------------------------------------------------------------
__global__ __launch_bounds__(TPB, 2)
void fused_kernel(const float* __restrict__ x, const float* __restrict__ state,
                  float* __restrict__ out)
{
    extern __shared__ __align__(1024) char sm[];
    const u32 smb = sm2u32(sm);
    const int tid = threadIdx.x;
    const int wid = tid >> 5;
    const int lane = tid & 31;

    // ---- B tile via cp.async, once per CTA ----
    {
        const uint4* sh = (const uint4*)g_Bhi;   // 1536 uint4
        #pragma unroll
        for (int j = 0; j < 6; j++) {
            int i = tid + j * TPB;
            cp_async16(smb + B_HI + 16 * i, sh + i);
        }
        asm volatile("cp.async.commit_group;");
    }

    // ---- tile range for this CTA (contiguous, balanced) ----
    const int G = gridDim.x;
    const int base = NTILES / G, rem = NTILES - base * G;
    const int b = blockIdx.x;
    const int cnt = base + (b < rem ? 1 : 0);
    const int start = b * base + (b < rem ? b : rem);

    // ---- prolog: tile `start` -> A0 ----
    {
        const float4* xs = (const float4*)x + (size_t)start * (RPT * 64);
        float4 v[8];
        #pragma unroll
        for (int j = 0; j < 8; j++) v[j] = __ldg(xs + tid + j * TPB);
        convert_sts(sm, A0, v, tid);
    }
    asm volatile("cp.async.wait_group 0;");
    __syncthreads();

    // ---- warp map: mw(m16) x kh(k-half) x nh(n-half of 48) ----
    const int mw = wid & 1;
    const int kh = (wid >> 1) & 1;
    const int nh = wid >> 2;

    const u32 sw    = (u32)(lane & 7);
    const u32 arow  = (u32)((mw * 16 + (lane & 15)) * 512);
    const u32 acolL = (u32)(lane >> 4);
    const u32 brow4 = (u32)((24 * nh + ((lane & 7) | ((lane >> 4) << 3))) * 512);
    const u32 brow2 = (u32)((24 * nh + 16 + (lane & 7)) * 512);
    const u32 bcolL = (u32)((lane >> 3) & 1);

    #pragma unroll 1
    for (int i = 0; i < cnt; i++) {
        const int tile = start + i;
        const u32 Acur = (i & 1) ? A1 : A0;
        const u32 Anxt = (i & 1) ? A0 : A1;
        const bool more = (i + 1 < cnt);

        // 1) issue next tile's loads (in flight through the MMA below)
        float4 v[8];
        if (more) {
            const float4* xs = (const float4*)x + (size_t)(tile + 1) * (RPT * 64);
            #pragma unroll
            for (int j = 0; j < 8; j++) v[j] = __ldg(xs + tid + j * TPB);
        }

        // 2) MMA on A[cur] (reads Acur + resident B)
        float c[3][4];
        #pragma unroll
        for (int n = 0; n < 3; n++)
            #pragma unroll
            for (int q = 0; q < 4; q++) c[n][q] = 0.0f;

        #pragma unroll
        for (int s = 0; s < 8; s++) {
            u32 step = (u32)(kh * 8 + s);
            u32 ac = ((step * 2u + acolL) ^ sw) << 4;
            u32 bc = ((step * 2u + bcolL) ^ sw) << 4;
            u32 ah[4], b0, b1, b2, b3, b4, b5;
            ldsm4(smb + Acur + arow + ac, ah[0], ah[1], ah[2], ah[3]);
            ldsm4(smb + B_HI + brow4 + bc, b0, b1, b2, b3);
            ldsm2(smb + B_HI + brow2 + bc, b4, b5);
            mma16816(c[0], ah, b0, b1);
            mma16816(c[1], ah, b2, b3);
            mma16816(c[2], ah, b4, b5);
        }

        // 3) stage C partials: cs[kh][row][col], row stride 50
        {
            float* cs = (float*)(sm + CS) + kh * (RPT * 50);
            int r0 = mw * 16 + (lane >> 2);
            int c0 = nh * 24 + 2 * (lane & 3);
            #pragma unroll
            for (int n = 0; n < 3; n++) {
                int col = c0 + n * 8;
                *(float2*)&cs[r0 * 50 + col]       = make_float2(c[n][0], c[n][1]);
                *(float2*)&cs[(r0 + 8) * 50 + col] = make_float2(c[n][2], c[n][3]);
            }
        }

        // 4) convert prefetched x -> A[next] (Anxt reads finished last iter)
        if (more) convert_sts(sm, Anxt, v, tid);

        __syncthreads();   // CS + A[next] complete; Acur reads done

        // 5) epilogue: linear DMP map, 2 threads per row (t-split)
        if (tid < 2 * RPT) {
            const int row  = tid & 31;
            const int half = tid >> 5;               // 0: t 0..5, 1: t 6..10
            const float* cs = (const float*)(sm + CS) + row * 50;
            float* eb = (float*)(sm + EB) + row * 77;
            const float* st = state + ((size_t)(tile * RPT + row)) * DOF;

            float g[DOF], y0v[DOF], ku[DOF], wv[DOF][NB];
            #pragma unroll
            for (int d = 0; d < DOF; d++) y0v[d] = __ldg(st + d);
            #pragma unroll
            for (int d = 0; d < DOF; d++) {
                g[d] = cs[d] + cs[RPT * 50 + d] + __ldg(g_bias48 + d);
                ku[d] = g[d] - y0v[d];
                #pragma unroll
                for (int j = 0; j < NB; j++) {
                    int col = DOF + 5 * d + j;
                    wv[d][j] = cs[col] + cs[RPT * 50 + col] + __ldg(g_bias48 + col);
                }
                if (half == 0) eb[d] = y0v[d];       // t = 0
            }
            int t0 = half ? 6 : 1, t1 = half ? 10 : 5;
            for (int t = t0; t <= t1; t++) {
                float a0 = c_A[t*8+0], a1 = c_A[t*8+1], a2 = c_A[t*8+2];
                float a3 = c_A[t*8+3], a4 = c_A[t*8+4], a5 = c_A[t*8+5];
                float a6 = c_A[t*8+6], a7 = c_A[t*8+7];
                #pragma unroll
                for (int d = 0; d < DOF; d++) {
                    float vv = a2 * wv[d][0];
                    vv = fmaf(a3, wv[d][1], vv);
                    vv = fmaf(a4, wv[d][2], vv);
                    vv = fmaf(a5, wv[d][3], vv);
                    vv = fmaf(a6, wv[d][4], vv);
                    float yv = fmaf(a0, y0v[d], a7);
                    yv = fmaf(a1, g[d], yv);
                    yv = fmaf(vv, ku[d], yv);
                    eb[t * 7 + d] = yv;
                }
            }
        }
        __syncthreads();   // EB complete; CS reads done (safe to rewrite next iter)

        // 6) coalesced output copy: 32*77 floats = 616 float4
        {
            const float4* s4 = (const float4*)(sm + EB);
            float4* d4 = (float4*)(out + (size_t)tile * (RPT * 77));
            #pragma unroll
            for (int j = 0; j < 3; j++) {
                int i2 = tid + j * TPB;
                if (i2 < (RPT * 77) / 4) d4[i2] = s4[i2];
            }
        }
        // next iter's CS writes happen after this thread's copy (program order)
        // and after sync2 for all other threads' EB reads. A[next] becomes cur.
    }
}

// ---------------------------------------------------------------------------
// Host: DMP linear map A (8 basis runs of the exact fp32 recursion).
// ---------------------------------------------------------------------------
static float hA[11 * 8];

static void compute_A_host() {
    float c[NB], s2[NB], P[100][NB];
    const float n15 = 11.180339887498949f;     // 5^1.5
    for (int j = 0; j < NB; j++) { c[j] = expf(-0.25f * j); s2[j] = n15 / c[j]; }
    float xv = 1.0f;
    for (int s = 0; s < 100; s++) {
        xv = xv - xv * 0.01f;
        float sum = 0.0f, psi[NB];
        for (int j = 0; j < NB; j++) {
            float d = xv - c[j];
            psi[j] = expf(-0.5f * d * d / s2[j]);
            sum += psi[j];
        }
        for (int j = 0; j < NB; j++) P[s][j] = psi[j] * xv / sum;
    }
    for (int b = 0; b < 8; b++) {              // basis: y0, g, u0..u4, const
        float y = (b == 0) ? 1.0f : 0.0f;
        float gb = (b == 1) ? 1.0f : 0.0f;
        float u[NB];
        for (int j = 0; j < NB; j++) u[j] = (b == 2 + j) ? 1.0f : 0.0f;
        float z = (b == 7) ? 0.05f : 0.0f;
        hA[0 * 8 + b] = y;
        int s = 0;
        for (int tt = 1; tt <= 10; tt++) {
            for (int ss = 0; ss < 10; ss++, s++) {
                float fx = 0.0f;
                for (int j = 0; j < NB; j++) fx += P[s][j] * u[j];
                float dz = 56.25f * (gb - y) - 15.0f * z + fx;
                y = y + z * 0.01f;             // uses old z
                z = z + dz * 0.01f;
            }
            hA[tt * 8 + b] = y;
        }
    }
}

extern "C" void kernel_launch(void* const* d_in, const int* in_sizes, int n_in,
                              void* d_out, int out_size)
{
    const float* x     = (const float*)d_in[0];
    const float* state = (const float*)d_in[1];
    const float* W     = (const float*)d_in[2];
    const float* b     = (const float*)d_in[3];
    float* out = (float*)d_out;

    compute_A_host();
    cudaMemcpyToSymbolAsync(c_A, hA, sizeof(hA), 0, cudaMemcpyHostToDevice);

    int sms = 148;
    cudaDeviceGetAttribute(&sms, cudaDevAttrMultiProcessorCount, 0);

    prep_w_kernel<<<48, 256>>>(W, b);
    cudaFuncSetAttribute(fused_kernel,
                         cudaFuncAttributeMaxDynamicSharedMemorySize, SMEM_TOTAL);
    fused_kernel<<<2 * sms, TPB, SMEM_TOTAL>>>(x, state, out);
}

// round 15
// speedup vs baseline: 1.2746x; 1.2746x over previous
#include <cuda_runtime.h>
#include <cuda_fp16.h>
#include <math.h>

typedef unsigned int u32;

#define DOF   7
#define NB    5
#define KDIM  256
#define OUTC  42
#define RPB   64
#define BATCH 65536
#define GRID  (BATCH / RPB)   // 1024
#define TPB   256

// ---- smem layout (bytes). Unpadded 512B rows, XOR-swizzled:
// phys16(r, c) = (c ^ (r & 7)), 16B units; conflict-free for STS/LDSM/cp.async.
#define A_HI   0                    // 64 x 512 = 32768 (x in fp16)
#define B_HI   32768                // 48 x 512 = 24576 -> 57344 (W fp16)
#define BIAS_S 57344                // 48 floats -> 57536
#define SMEM_TOTAL 57600            // x3 CTAs = 172800 < SM limit
// aliases after MMA (A tile dead):
#define CS     0                    // 2 x (64*50*4) = 25600
#define EB     25600                // 64*77*4 = 19712 -> 45312 < B_HI? no: overlaps B?
// EB ends at 45312 > 32768: EB overlaps B_HI region. B reads are done before the
// epilogue writes EB (post-MMA sync), and B is not reused afterwards -> safe.

// Pre-converted, PRE-SWIZZLED W tile (exact smem byte layout, 48x512B)
__device__ __align__(16) unsigned short g_Bhi[48 * 256];
__device__ __align__(16) float g_bias48[48];

// DMP linear map: y[t] = A[t] . [y0, g, u0..u4, 1]
__constant__ float c_A[11 * 8];

__device__ __forceinline__ u32 sm2u32(const void* p) {
    u32 a; asm("{.reg .u64 t; cvta.to.shared.u64 t,%1; cvt.u32.u64 %0,t;}"
               : "=r"(a) : "l"(p));
    return a;
}
__device__ __forceinline__ void ldsm4(u32 addr, u32& r0, u32& r1, u32& r2, u32& r3) {
    asm volatile("ldmatrix.sync.aligned.m8n8.x4.shared.b16 {%0,%1,%2,%3},[%4];"
                 : "=r"(r0), "=r"(r1), "=r"(r2), "=r"(r3) : "r"(addr));
}
__device__ __forceinline__ void ldsm2(u32 addr, u32& r0, u32& r1) {
    asm volatile("ldmatrix.sync.aligned.m8n8.x2.shared.b16 {%0,%1},[%2];"
                 : "=r"(r0), "=r"(r1) : "r"(addr));
}
__device__ __forceinline__ void mma16816(float* c, const u32* a, u32 b0, u32 b1) {
    asm volatile(
        "mma.sync.aligned.m16n8k16.row.col.f32.f16.f16.f32 "
        "{%0,%1,%2,%3},{%4,%5,%6,%7},{%8,%9},{%0,%1,%2,%3};"
        : "+f"(c[0]), "+f"(c[1]), "+f"(c[2]), "+f"(c[3])
        : "r"(a[0]), "r"(a[1]), "r"(a[2]), "r"(a[3]), "r"(b0), "r"(b1));
}
__device__ __forceinline__ void cp_async16(u32 dst, const void* src) {
    asm volatile("cp.async.cg.shared.global [%0],[%1],16;" :: "r"(dst), "l"(src));
}

// ---------------------------------------------------------------------------
// Prep (once): W -> fp16, stored pre-swizzled:
//   short-off(n, k) = n*256 + (((k>>3) ^ (n&7)) << 3) + (k&7)
// ---------------------------------------------------------------------------
__global__ void prep_w_kernel(const float* __restrict__ W,
                              const float* __restrict__ bias)
{
    int gid = blockIdx.x * 256 + threadIdx.x;   // 48*256 = 12288 threads
    int n = gid >> 8, k = gid & 255;
    unsigned short hi = 0;
    if (n < OUTC) {
        float w = __ldg(W + k * OUTC + n);
        __half h = __float2half_rn(w);
        hi = *(const unsigned short*)&h;
    }
    int off = n * 256 + (((k >> 3) ^ (n & 7)) << 3) + (k & 7);
    g_Bhi[off] = hi;
    if (gid < 48) g_bias48[gid] = (gid < OUTC) ? __ldg(bias + gid) : 0.0f;
}

// ---------------------------------------------------------------------------
__global__ __launch_bounds__(TPB, 3)
void fused_kernel(const float* __restrict__ x, const float* __restrict__ state,
                  float* __restrict__ out)
{
    extern __shared__ __align__(1024) char sm[];
    const u32 smb = sm2u32(sm);
    const int tid = threadIdx.x;
    const int wid = tid >> 5;
    const int lane = tid & 31;

    // ---- B tile via cp.async; bias -> smem ----
    {
        const uint4* sh = (const uint4*)g_Bhi;   // 1536 uint4
        #pragma unroll
        for (int j = 0; j < 6; j++) {
            int i = tid + j * TPB;
            cp_async16(smb + B_HI + 16 * i, sh + i);
        }
        asm volatile("cp.async.commit_group;");
        if (tid < 48) ((float*)(sm + BIAS_S))[tid] = g_bias48[tid];
    }

    // ---- x -> fp16 into swizzled A tile; batched loads for high MLP ----
    const float4* xsrc = (const float4*)(x + (size_t)blockIdx.x * RPB * KDIM);
    #pragma unroll
    for (int h = 0; h < 2; h++) {
        float4 v[8];
        #pragma unroll
        for (int j = 0; j < 8; j++)
            v[j] = __ldg(xsrc + tid + (h * 8 + j) * TPB);
        #pragma unroll
        for (int j = 0; j < 8; j++) {
            int idx = tid + (h * 8 + j) * TPB;
            int r = idx >> 6, k4 = idx & 63;
            __half2 h01 = __floats2half2_rn(v[j].x, v[j].y);
            __half2 h23 = __floats2half2_rn(v[j].z, v[j].w);
            u32 off = (u32)(r * 512) + ((((u32)k4 >> 1) ^ ((u32)r & 7u)) << 4)
                    + ((u32)k4 & 1u) * 8u;
            *(uint2*)(sm + A_HI + off) =
                make_uint2(*(const u32*)&h01, *(const u32*)&h23);
        }
    }
    asm volatile("cp.async.wait_group 0;");
    __syncthreads();

    // ---- MMA: 8 warps = 2 m-tiles(32) x 2 k-halves x 2 n-halves(24) ----
    const int mw = wid & 1;            // m-tile: rows mw*32..+31
    const int kh = (wid >> 1) & 1;     // k-half: k16 steps kh*8..+7
    const int nh = wid >> 2;           // n-half: cols nh*24..+23

    float c[2][3][4];
    #pragma unroll
    for (int s2 = 0; s2 < 2; s2++)
        #pragma unroll
        for (int n = 0; n < 3; n++)
            #pragma unroll
            for (int q = 0; q < 4; q++) c[s2][n][q] = 0.0f;

    const u32 sw    = (u32)(lane & 7);           // swizzle constant (row&7)
    const u32 arow  = (u32)((mw * 32 + (lane & 15)) * 512);
    const u32 acolL = (u32)(lane >> 4);
    const u32 brow4 = (u32)((nh * 24 + ((lane & 7) | ((lane >> 4) << 3))) * 512);
    const u32 brow2 = (u32)((nh * 24 + 16 + (lane & 7)) * 512);
    const u32 bcolL = (u32)((lane >> 3) & 1);

    #pragma unroll
    for (int s = 0; s < 8; s++) {
        u32 step = (u32)(kh * 8 + s);                // k16 step 0..15
        u32 ac = ((step * 2u + acolL) ^ sw) << 4;
        u32 bc = ((step * 2u + bcolL) ^ sw) << 4;
        u32 ah[2][4], b0, b1, b2, b3, b4, b5;
        #pragma unroll
        for (int sub = 0; sub < 2; sub++) {
            u32 ad = arow + (u32)sub * (16u * 512u) + ac;
            ldsm4(smb + A_HI + ad, ah[sub][0], ah[sub][1], ah[sub][2], ah[sub][3]);
        }
        ldsm4(smb + B_HI + brow4 + bc, b0, b1, b2, b3);
        ldsm2(smb + B_HI + brow2 + bc, b4, b5);
        #pragma unroll
        for (int sub = 0; sub < 2; sub++) {
            mma16816(c[sub][0], ah[sub], b0, b1);
            mma16816(c[sub][1], ah[sub], b2, b3);
            mma16816(c[sub][2], ah[sub], b4, b5);
        }
    }
    __syncthreads();   // tile reads done before aliases are written

    // ---- stage C partials: cs[kh][row][col], row stride 50 floats ----
    {
        float* cs = (float*)(sm + CS) + kh * (RPB * 50);
        int c0 = nh * 24 + 2 * (lane & 3);
        #pragma unroll
        for (int sub = 0; sub < 2; sub++) {
            int r0 = mw * 32 + sub * 16 + (lane >> 2);
            #pragma unroll
            for (int n = 0; n < 3; n++) {
                int col = c0 + n * 8;
                *(float2*)&cs[r0 * 50 + col]       = make_float2(c[sub][n][0], c[sub][n][1]);
                *(float2*)&cs[(r0 + 8) * 50 + col] = make_float2(c[sub][n][2], c[sub][n][3]);
            }
        }
    }
    __syncthreads();

    // ---- epilogue: linear DMP map, 2 threads per row (t-split) ----
    if (tid < 2 * RPB) {
        const int row  = tid & 63;
        const int half = tid >> 6;                   // 0: t 0..5, 1: t 6..10
        const float2* c0p = (const float2*)((const float*)(sm + CS) + row * 50);
        const float2* c1p = (const float2*)((const float*)(sm + CS)
                                            + RPB * 50 + row * 50);
        const float2* bi2 = (const float2*)(sm + BIAS_S);
        float* eb = (float*)(sm + EB) + row * 77;
        const float* st = state + ((size_t)(blockIdx.x * RPB + row)) * DOF;

        float cv[42];
        #pragma unroll
        for (int p = 0; p < 21; p++) {
            float2 a = c0p[p], b = c1p[p], bb = bi2[p];
            cv[2 * p]     = a.x + b.x + bb.x;
            cv[2 * p + 1] = a.y + b.y + bb.y;
        }

        float y0v[DOF], ku[DOF];
        #pragma unroll
        for (int d = 0; d < DOF; d++) y0v[d] = __ldg(st + d);
        #pragma unroll
        for (int d = 0; d < DOF; d++) {
            ku[d] = cv[d] - y0v[d];
            if (half == 0) eb[d] = y0v[d];           // t = 0
        }
        int t0 = half ? 6 : 1, t1 = half ? 10 : 5;
        for (int t = t0; t <= t1; t++) {
            float a0 = c_A[t*8+0], a1 = c_A[t*8+1], a2 = c_A[t*8+2], a3 = c_A[t*8+3];
            float a4 = c_A[t*8+4], a5 = c_A[t*8+5], a6 = c_A[t*8+6], a7 = c_A[t*8+7];
            #pragma unroll
            for (int d = 0; d < DOF; d++) {
                const float* wd = cv + DOF + 5 * d;
                float v = a2 * wd[0];
                v = fmaf(a3, wd[1], v);
                v = fmaf(a4, wd[2], v);
                v = fmaf(a5, wd[3], v);
                v = fmaf(a6, wd[4], v);
                float yv = fmaf(a0, y0v[d], a7);
                yv = fmaf(a1, cv[d], yv);
                yv = fmaf(v, ku[d], yv);
                eb[t * 7 + d] = yv;
            }
        }
    }
    __syncthreads();

    // ---- coalesced output copy: 64*77 floats = 1232 float4 ----
    const float4* s4 = (const float4*)(sm + EB);
    float4* d4 = (float4*)(out + (size_t)blockIdx.x * RPB * 77);
    #pragma unroll
    for (int j = 0; j < 5; j++) {
        int i = tid + j * TPB;
        if (i < (RPB * 77) / 4) d4[i] = s4[i];
    }
}

// ---------------------------------------------------------------------------
// Host: DMP linear map A (8 basis runs of the exact fp32 recursion).
// ---------------------------------------------------------------------------
static float hA[11 * 8];

static void compute_A_host() {
    float c[NB], s2[NB], P[100][NB];
    const float n15 = 11.180339887498949f;     // 5^1.5
    for (int j = 0; j < NB; j++) { c[j] = expf(-0.25f * j); s2[j] = n15 / c[j]; }
    float xv = 1.0f;
    for (int s = 0; s < 100; s++) {
        xv = xv - xv * 0.01f;
        float sum = 0.0f, psi[NB];
        for (int j = 0; j < NB; j++) {
            float d = xv - c[j];
            psi[j] = expf(-0.5f * d * d / s2[j]);
            sum += psi[j];
        }
        for (int j = 0; j < NB; j++) P[s][j] = psi[j] * xv / sum;
    }
    for (int b = 0; b < 8; b++) {              // basis: y0, g, u0..u4, const
        float y = (b == 0) ? 1.0f : 0.0f;
        float gb = (b == 1) ? 1.0f : 0.0f;
        float u[NB];
        for (int j = 0; j < NB; j++) u[j] = (b == 2 + j) ? 1.0f : 0.0f;
        float z = (b == 7) ? 0.05f : 0.0f;
        hA[0 * 8 + b] = y;
        int s = 0;
        for (int tt = 1; tt <= 10; tt++) {
            for (int ss = 0; ss < 10; ss++, s++) {
                float fx = 0.0f;
                for (int j = 0; j < NB; j++) fx += P[s][j] * u[j];
                float dz = 56.25f * (gb - y) - 15.0f * z + fx;
                y = y + z * 0.01f;             // uses old z
                z = z + dz * 0.01f;
            }
            hA[tt * 8 + b] = y;
        }
    }
}

extern "C" void kernel_launch(void* const* d_in, const int* in_sizes, int n_in,
                              void* d_out, int out_size)
{
    const float* x     = (const float*)d_in[0];
    const float* state = (const float*)d_in[1];
    const float* W     = (const float*)d_in[2];
    const float* b     = (const float*)d_in[3];
    float* out = (float*)d_out;

    compute_A_host();
    cudaMemcpyToSymbolAsync(c_A, hA, sizeof(hA), 0, cudaMemcpyHostToDevice);

    prep_w_kernel<<<48, 256>>>(W, b);
    cudaFuncSetAttribute(fused_kernel,
                         cudaFuncAttributeMaxDynamicSharedMemorySize, SMEM_TOTAL);
    fused_kernel<<<GRID, TPB, SMEM_TOTAL>>>(x, state, out);
}